// round 14
// baseline (speedup 1.0000x reference)
#include <cuda_runtime.h>
#include <cuda_fp16.h>
#include <stdint.h>
#include <stddef.h>

// ---------------------------------------------------------------------------
// out = softmax(Q K^T / sqrt(D) + tril(ones)) V ;  B=16, S=2048, D=3072, fp32
// sm_103 base-target only: cp.async + ldmatrix + mma.sync (no tcgen05/TMA).
// R9 GEMM config (best). V conversion fused into GEMM1's epilogue tail:
// GEMM1 fully occupies the RF (2x256x128 regs = 64K), so no other kernel can
// ever co-run with it -- the only way to overlap the HBM-bound V convert with
// GEMM1's compute (DRAM 6.8%) is to run it from GEMM1's own CTAs.
// ---------------------------------------------------------------------------
#define BB 16
#define SS 2048
#define DD 3072
#define SCALE 0.01804219591217581f  // 1/sqrt(3072)

// fp16 scratch, block-swizzled: block = 128 rows x 64 halves (16KB), SW128
// swizzle inside block (byte ^ ((byte>>3)&0x70)); blocks contiguous.
__device__ __align__(128) __half g_Qh[(size_t)BB * SS * DD];   // (b, sT16, kT48)
__device__ __align__(128) __half g_Kh[(size_t)BB * SS * DD];   // (b, tT16, kT48)
__device__ __align__(128) __half g_Vt[(size_t)BB * SS * DD];   // (b, dT24, kT32) row=d,col=t
__device__ __align__(128) __half g_P [(size_t)BB * SS * SS];   // (b, sT16, tT32)
__device__ __align__(128) float  g_rs[(size_t)BB * SS * 32];   // 32 partial rowsums per row

#define SWZ(o) ((o) ^ (((o) >> 3) & 0x70))

static __device__ __forceinline__ uint32_t smem_u32(const void* p) {
    uint32_t a;
    asm("{ .reg .u64 t; cvta.to.shared.u64 t, %1; cvt.u32.u64 %0, t; }" : "=r"(a) : "l"(p));
    return a;
}
static __device__ __forceinline__ void cp16(uint32_t dst, const void* src) {
    unsigned long long g = __cvta_generic_to_global(src);
    asm volatile("cp.async.cg.shared.global [%0], [%1], 16;" :: "r"(dst), "l"(g) : "memory");
}
#define CP_COMMIT() asm volatile("cp.async.commit_group;" ::: "memory")
#define CP_WAIT1()  asm volatile("cp.async.wait_group 1;" ::: "memory")
#define CP_WAIT0()  asm volatile("cp.async.wait_group 0;" ::: "memory")

static __device__ __forceinline__ void ldsm4(uint32_t* r, uint32_t addr) {
    asm volatile("ldmatrix.sync.aligned.m8n8.x4.shared.b16 {%0,%1,%2,%3}, [%4];"
                 : "=r"(r[0]), "=r"(r[1]), "=r"(r[2]), "=r"(r[3]) : "r"(addr));
}
static __device__ __forceinline__ void hmma(float* d, const uint32_t* a, const uint32_t* b) {
    asm volatile(
        "mma.sync.aligned.m16n8k16.row.col.f32.f16.f16.f32 "
        "{%0,%1,%2,%3}, {%4,%5,%6,%7}, {%8,%9}, {%0,%1,%2,%3};"
        : "+f"(d[0]), "+f"(d[1]), "+f"(d[2]), "+f"(d[3])
        : "r"(a[0]), "r"(a[1]), "r"(a[2]), "r"(a[3]), "r"(b[0]), "r"(b[1]));
}

// ---------------------------------------------------------------------------
// fp32 -> fp16 block-swizzled convert for Q / K (row=s, col=k)
// grid (48, 16, 16), 256 threads
// ---------------------------------------------------------------------------
template<int W>
__global__ __launch_bounds__(256) void k_conv_qk(const float* __restrict__ src) {
    __half* dst = W ? g_Kh : g_Qh;
    const int kT = blockIdx.x, sT = blockIdx.y, b = blockIdx.z, tid = threadIdx.x;
    const float* s0 = src + ((size_t)(b * SS) + sT * 128) * DD + kT * 64;
    __half* d0 = dst + ((size_t)((b * 16 + sT) * 48 + kT)) * 8192;
#pragma unroll
    for (int j = 0; j < 4; j++) {
        int e = (j * 256 + tid) * 8;
        int r = e >> 6, c = e & 63;
        const float4* p = (const float4*)(s0 + (size_t)r * DD + c);
        float4 f0 = p[0], f1 = p[1];
        __half2 h0 = __floats2half2_rn(f0.x, f0.y), h1 = __floats2half2_rn(f0.z, f0.w);
        __half2 h2 = __floats2half2_rn(f1.x, f1.y), h3 = __floats2half2_rn(f1.z, f1.w);
        uint4 u;
        u.x = *(const uint32_t*)&h0; u.y = *(const uint32_t*)&h1;
        u.z = *(const uint32_t*)&h2; u.w = *(const uint32_t*)&h3;
        *(uint4*)((char*)d0 + SWZ((uint32_t)(r * 128 + c * 2))) = u;
    }
}

// ---------------------------------------------------------------------------
// GEMM: CTA 128x128, K-chunk 64, 3-stage cp.async pipeline (32KB/stage),
// 256 threads / 8 warps (4m x 2n), warp tile 32x64, 2 CTAs per SM.
// MODE 0: exp epilogue -> P (fp16 swizzled) + partial rowsums, then each CTA
//         converts 3 of the 12288 V tiles (fp32 -> fp16 transposed swizzled)
//         so the V convert overlaps other CTAs' compute.
// MODE 1: normalize epilogue -> fp32 out
// ---------------------------------------------------------------------------
#define STAGE_BYTES 32768
#define SMEM_BYTES  (3 * STAGE_BYTES + 1024)

template<int NK, int NBT, int MODE>
__global__ __launch_bounds__(256, 2) void k_gemm(
    const __half* __restrict__ Ab, const __half* __restrict__ Bb,
    float* __restrict__ out, const float* __restrict__ vsrc)
{
    extern __shared__ __align__(1024) char sm[];
    const int tid = threadIdx.x, wid = tid >> 5, lane = tid & 31;
    const int nT = blockIdx.x, sT = blockIdx.y, b = blockIdx.z;
    const uint32_t smb = smem_u32(sm);
    float* sinv = (float*)(sm + 3 * STAGE_BYTES);

    const __half* aBase = Ab + ((size_t)(b * 16 + sT) * NK) * 8192;
    const __half* bBase = Bb + ((size_t)(b * NBT + nT) * NK) * 8192;

    if (MODE == 1 && tid < 128) {
        const float* rr = g_rs + ((size_t)(b * SS) + sT * 128 + tid) * 32;
        float s = 0.f;
#pragma unroll
        for (int i = 0; i < 8; i++) {
            float4 v = *(const float4*)(rr + i * 4);
            s += v.x + v.y + v.z + v.w;
        }
        sinv[tid] = 1.f / s;
    }

    // copy chunk k (A 16KB + B 16KB) into stage k%3; one commit group
    auto issue = [&](int k) {
        uint32_t st = smb + (uint32_t)(k % 3) * STAGE_BYTES;
#pragma unroll
        for (int j = 0; j < 8; j++) {
            int idx = j * 256 + tid;
            int blk = idx >> 10, ru = idx & 1023;
            const char* src = (const char*)((blk ? bBase : aBase) +
                              (size_t)k * 8192) + ru * 16;
            cp16(st + (uint32_t)blk * 16384u + (uint32_t)ru * 16u, src);
        }
        CP_COMMIT();
    };
    issue(0); issue(1);

    float acc[2][8][4];
#pragma unroll
    for (int i = 0; i < 2; i++)
#pragma unroll
        for (int j = 0; j < 8; j++)
#pragma unroll
            for (int q = 0; q < 4; q++) acc[i][j][q] = 0.f;

    const int wm = wid & 3, wn = wid >> 2;       // 4 m-groups x 2 n-groups
    const int g2 = lane >> 3, ri = lane & 7;
    const int arow = wm * 32 + (g2 & 1) * 8 + ri;
    const int brow = wn * 64 + (g2 & 1) * 8 + ri;

    // SWZ(row*128+col) = row*128 + (col ^ ((row&7)*16)); fold invariants.
    const uint32_t colhi = (uint32_t)(g2 >> 1) * 16;
    const uint32_t cba = colhi ^ ((uint32_t)(arow & 7) * 16);
    const uint32_t cbb = colhi ^ ((uint32_t)(brow & 7) * 16);
    const uint32_t aoffc = (uint32_t)arow * 128;
    const uint32_t boffc = 16384u + (uint32_t)brow * 128;

    for (int k = 0; k < NK; k++) {
        CP_WAIT1();                      // own part of chunk k resident
        __syncthreads();                 // publish writes; retire reads of k-1
        if (k + 2 < NK) issue(k + 2); else CP_COMMIT();   // stage (k+2)%3 freed above
        uint32_t sa = smb + (uint32_t)(k % 3) * STAGE_BYTES;
#pragma unroll
        for (int kss = 0; kss < 4; kss++) {
            const uint32_t ca = cba ^ (uint32_t)(kss * 32);
            const uint32_t cb = cbb ^ (uint32_t)(kss * 32);
            uint32_t af[2][4], bf[8][2];
#pragma unroll
            for (int mf = 0; mf < 2; mf++)
                ldsm4(af[mf], sa + aoffc + (uint32_t)(mf * 2048) + ca);
#pragma unroll
            for (int f = 0; f < 4; f++) {
                uint32_t tb4[4];
                ldsm4(tb4, sa + boffc + (uint32_t)(f * 2048) + cb);
                bf[2 * f][0] = tb4[0]; bf[2 * f + 1][0] = tb4[1];
                bf[2 * f][1] = tb4[2]; bf[2 * f + 1][1] = tb4[3];
            }
#pragma unroll
            for (int mf = 0; mf < 2; mf++)
#pragma unroll
                for (int nf = 0; nf < 8; nf++)
                    hmma(acc[mf][nf], af[mf], bf[nf]);
        }
    }
    CP_WAIT0();
    __syncthreads();

    const int g = lane >> 2, t4 = lane & 3;

    if (MODE == 0) {
#pragma unroll
        for (int mf = 0; mf < 2; mf++) {
#pragma unroll
            for (int hi = 0; hi < 2; hi++) {
                int row = wm * 32 + mf * 16 + hi * 8 + g;
                int sglob = sT * 128 + row;
                float rsum = 0.f;
#pragma unroll
                for (int nf = 0; nf < 8; nf++) {
                    int c = wn * 64 + nf * 8 + 2 * t4;
                    int tg = nT * 128 + c;
                    float x0 = acc[mf][nf][hi * 2]     * SCALE + ((tg     <= sglob) ? 1.f : 0.f);
                    float x1 = acc[mf][nf][hi * 2 + 1] * SCALE + ((tg + 1 <= sglob) ? 1.f : 0.f);
                    float p0 = __expf(x0), p1 = __expf(x1);
                    rsum += p0 + p1;
                    __half2 h = __floats2half2_rn(p0, p1);
                    uint32_t off = (uint32_t)(c >> 6) * 16384 +
                                   SWZ((uint32_t)(row * 128 + (c & 63) * 2));
                    *(__half2*)(sm + off) = h;
                }
                rsum += __shfl_xor_sync(~0u, rsum, 1);
                rsum += __shfl_xor_sync(~0u, rsum, 2);
                if (t4 == 0)
                    g_rs[((size_t)(b * SS) + sglob) * 32 + nT * 2 + wn] = rsum;
            }
        }
        __syncthreads();
        __half* pdst = g_P + ((size_t)((b * 16 + sT) * 32 + nT * 2)) * 8192;
        const uint4* s4 = (const uint4*)sm;
        uint4* g4 = (uint4*)pdst;
        for (int i = tid; i < 2048; i += 256) g4[i] = s4[i];

        // ---- fused V conversion: 3 of 12288 tiles per CTA ----
        __syncthreads();                 // P-store smem reads done; reuse sm
        const int cid = (b * 16 + sT) * 16 + nT;   // 0..4095
#pragma unroll
        for (int i = 0; i < 3; i++) {
            int t = cid * 3 + i;
            int vb = t / 768, rem = t - vb * 768;
            int dT = rem >> 5, kT = rem & 31;
            const float* s0 = vsrc + ((size_t)(vb * SS) + kT * 64) * DD + dT * 128;
            char* tb = sm + i * 16384;
#pragma unroll
            for (int j = 0; j < 8; j++) {
                int e = (j * 256 + tid) * 4;
                int tt = e >> 7, dd = e & 127;
                float4 f = *(const float4*)(s0 + (size_t)tt * DD + dd);
                *(__half*)(tb + SWZ((uint32_t)((dd + 0) * 128 + tt * 2))) = __float2half_rn(f.x);
                *(__half*)(tb + SWZ((uint32_t)((dd + 1) * 128 + tt * 2))) = __float2half_rn(f.y);
                *(__half*)(tb + SWZ((uint32_t)((dd + 2) * 128 + tt * 2))) = __float2half_rn(f.z);
                *(__half*)(tb + SWZ((uint32_t)((dd + 3) * 128 + tt * 2))) = __float2half_rn(f.w);
            }
        }
        __syncthreads();
#pragma unroll
        for (int i = 0; i < 3; i++) {
            int t = cid * 3 + i;
            int vb = t / 768, rem = t - vb * 768;
            int dT = rem >> 5, kT = rem & 31;
            __half* d0 = g_Vt + ((size_t)((vb * 24 + dT) * 32 + kT)) * 8192;
            const uint4* s4v = (const uint4*)(sm + i * 16384);
            uint4* g4v = (uint4*)d0;
            for (int ii = tid; ii < 1024; ii += 256) g4v[ii] = s4v[ii];
        }
    } else {
#pragma unroll
        for (int mf = 0; mf < 2; mf++) {
#pragma unroll
            for (int hi = 0; hi < 2; hi++) {
                int row = wm * 32 + mf * 16 + hi * 8 + g;
                float inv = sinv[row];
#pragma unroll
                for (int nf = 0; nf < 8; nf++) {
                    int c = wn * 64 + nf * 8 + 2 * t4;
                    float2 v;
                    v.x = acc[mf][nf][hi * 2]     * inv;
                    v.y = acc[mf][nf][hi * 2 + 1] * inv;
                    *(float2*)(sm + (size_t)(row * 132 + c) * 4) = v;
                }
            }
        }
        __syncthreads();
        float* obase = out + ((size_t)(b * SS) + sT * 128) * DD + nT * 128;
        for (int i = tid; i < 4096; i += 256) {
            int row = i >> 5, c = (i & 31) * 4;
            float4 v = *(const float4*)(sm + (size_t)(row * 132 + c) * 4);
            *(float4*)(obase + (size_t)row * DD + c) = v;
        }
    }
}

// ---------------------------------------------------------------------------
extern "C" void kernel_launch(void* const* d_in, const int* in_sizes, int n_in,
                              void* d_out, int out_size) {
    (void)in_sizes; (void)n_in; (void)out_size;
    const float* q = (const float*)d_in[1];
    const float* k = (const float*)d_in[2];
    const float* v = (const float*)d_in[3];
    float* out = (float*)d_out;

    static int init = 0;
    if (!init) {
        cudaFuncSetAttribute(k_gemm<48, 16, 0>, cudaFuncAttributeMaxDynamicSharedMemorySize, SMEM_BYTES);
        cudaFuncSetAttribute(k_gemm<32, 24, 1>, cudaFuncAttributeMaxDynamicSharedMemorySize, SMEM_BYTES);
        init = 1;
    }

    void *pQ = nullptr, *pK = nullptr, *pVt = nullptr, *pP = nullptr;
    cudaGetSymbolAddress(&pQ, g_Qh);
    cudaGetSymbolAddress(&pK, g_Kh);
    cudaGetSymbolAddress(&pVt, g_Vt);
    cudaGetSymbolAddress(&pP, g_P);

    k_conv_qk<0><<<dim3(48, 16, 16), 256>>>(q);
    k_conv_qk<1><<<dim3(48, 16, 16), 256>>>(k);
    // GEMM1: logits -> exp -> P + rowsums, with fused V convert in the tail.
    k_gemm<48, 16, 0><<<dim3(16, 16, 16), 256, SMEM_BYTES>>>(
        (const __half*)pQ, (const __half*)pK, nullptr, v);
    // GEMM2: P @ Vt -> normalized out. grid (nT=24, sT=16, b=16)
    k_gemm<32, 24, 1><<<dim3(24, 16, 16), 256, SMEM_BYTES>>>(
        (const __half*)pP, (const __half*)pVt, out, nullptr);
}

// round 15
// speedup vs baseline: 1.0479x; 1.0479x over previous
#include <cuda_runtime.h>
#include <cuda_fp16.h>
#include <stdint.h>
#include <stddef.h>

// ---------------------------------------------------------------------------
// out = softmax(Q K^T / sqrt(D) + tril(ones)) V ;  B=16, S=2048, D=3072, fp32
// sm_103 base-target only: cp.async + ldmatrix + mma.sync (no tcgen05/TMA).
// R9/R12 GEMM tiling (best) with the wait_group+__syncthreads chunk rendezvous
// replaced by a per-stage mbarrier pipeline (full: 256 cp.async arrivals,
// empty: 256 thread arrivals) so warps decouple instead of lockstepping.
// ---------------------------------------------------------------------------
#define BB 16
#define SS 2048
#define DD 3072
#define SCALE 0.01804219591217581f  // 1/sqrt(3072)

// fp16 scratch, block-swizzled: block = 128 rows x 64 halves (16KB), SW128
// swizzle inside block (byte ^ ((byte>>3)&0x70)); blocks contiguous.
__device__ __align__(128) __half g_Qh[(size_t)BB * SS * DD];   // (b, sT16, kT48)
__device__ __align__(128) __half g_Kh[(size_t)BB * SS * DD];   // (b, tT16, kT48)
__device__ __align__(128) __half g_Vt[(size_t)BB * SS * DD];   // (b, dT24, kT32) row=d,col=t
__device__ __align__(128) __half g_P [(size_t)BB * SS * SS];   // (b, sT16, tT32)
__device__ __align__(128) float  g_rs[(size_t)BB * SS * 32];   // 32 partial rowsums per row

#define SWZ(o) ((o) ^ (((o) >> 3) & 0x70))

static __device__ __forceinline__ uint32_t smem_u32(const void* p) {
    uint32_t a;
    asm("{ .reg .u64 t; cvta.to.shared.u64 t, %1; cvt.u32.u64 %0, t; }" : "=r"(a) : "l"(p));
    return a;
}
static __device__ __forceinline__ void cp16(uint32_t dst, const void* src) {
    unsigned long long g = __cvta_generic_to_global(src);
    asm volatile("cp.async.cg.shared.global [%0], [%1], 16;" :: "r"(dst), "l"(g) : "memory");
}
static __device__ __forceinline__ void mbar_init(uint32_t a, uint32_t c) {
    asm volatile("mbarrier.init.shared.b64 [%0], %1;" :: "r"(a), "r"(c) : "memory");
}
static __device__ __forceinline__ void mbar_arrive(uint32_t a) {
    asm volatile("mbarrier.arrive.shared.b64 _, [%0];" :: "r"(a) : "memory");
}
// arrive on mbar once all of THIS thread's prior cp.asyncs have completed
static __device__ __forceinline__ void cpasync_mbar_arrive(uint32_t a) {
    asm volatile("cp.async.mbarrier.arrive.noinc.shared::cta.b64 [%0];" :: "r"(a) : "memory");
}
static __device__ __forceinline__ void mbar_wait(uint32_t mbar, uint32_t parity) {
    uint32_t done = 0;
    while (!done) {
        asm volatile(
            "{\n\t.reg .pred p;\n\t"
            "mbarrier.try_wait.parity.acquire.cta.shared::cta.b64 p, [%1], %2, 0x989680;\n\t"
            "selp.b32 %0, 1, 0, p;\n\t}"
            : "=r"(done) : "r"(mbar), "r"(parity) : "memory");
    }
}

static __device__ __forceinline__ void ldsm4(uint32_t* r, uint32_t addr) {
    asm volatile("ldmatrix.sync.aligned.m8n8.x4.shared.b16 {%0,%1,%2,%3}, [%4];"
                 : "=r"(r[0]), "=r"(r[1]), "=r"(r[2]), "=r"(r[3]) : "r"(addr));
}
static __device__ __forceinline__ void hmma(float* d, const uint32_t* a, const uint32_t* b) {
    asm volatile(
        "mma.sync.aligned.m16n8k16.row.col.f32.f16.f16.f32 "
        "{%0,%1,%2,%3}, {%4,%5,%6,%7}, {%8,%9}, {%0,%1,%2,%3};"
        : "+f"(d[0]), "+f"(d[1]), "+f"(d[2]), "+f"(d[3])
        : "r"(a[0]), "r"(a[1]), "r"(a[2]), "r"(a[3]), "r"(b[0]), "r"(b[1]));
}

// ---------------------------------------------------------------------------
// fp32 -> fp16 block-swizzled convert for Q / K (row=s, col=k)
// grid (48, 16, 16), 256 threads
// ---------------------------------------------------------------------------
template<int W>
__global__ __launch_bounds__(256) void k_conv_qk(const float* __restrict__ src) {
    __half* dst = W ? g_Kh : g_Qh;
    const int kT = blockIdx.x, sT = blockIdx.y, b = blockIdx.z, tid = threadIdx.x;
    const float* s0 = src + ((size_t)(b * SS) + sT * 128) * DD + kT * 64;
    __half* d0 = dst + ((size_t)((b * 16 + sT) * 48 + kT)) * 8192;
#pragma unroll
    for (int j = 0; j < 4; j++) {
        int e = (j * 256 + tid) * 8;
        int r = e >> 6, c = e & 63;
        const float4* p = (const float4*)(s0 + (size_t)r * DD + c);
        float4 f0 = p[0], f1 = p[1];
        __half2 h0 = __floats2half2_rn(f0.x, f0.y), h1 = __floats2half2_rn(f0.z, f0.w);
        __half2 h2 = __floats2half2_rn(f1.x, f1.y), h3 = __floats2half2_rn(f1.z, f1.w);
        uint4 u;
        u.x = *(const uint32_t*)&h0; u.y = *(const uint32_t*)&h1;
        u.z = *(const uint32_t*)&h2; u.w = *(const uint32_t*)&h3;
        *(uint4*)((char*)d0 + SWZ((uint32_t)(r * 128 + c * 2))) = u;
    }
}

// ---------------------------------------------------------------------------
// V fp32 -> fp16 transposed block-swizzled (row=d, col=t), grid (32, 24, 16)
// ---------------------------------------------------------------------------
__global__ __launch_bounds__(256) void k_conv_v(const float* __restrict__ src) {
    __shared__ __align__(16) char tb[16384];
    const int kT = blockIdx.x, dT = blockIdx.y, b = blockIdx.z, tid = threadIdx.x;
    const float* s0 = src + ((size_t)(b * SS) + kT * 64) * DD + dT * 128;
#pragma unroll
    for (int j = 0; j < 8; j++) {
        int e = (j * 256 + tid) * 4;
        int tt = e >> 7, dd = e & 127;
        float4 f = *(const float4*)(s0 + (size_t)tt * DD + dd);
        *(__half*)(tb + SWZ((uint32_t)((dd + 0) * 128 + tt * 2))) = __float2half_rn(f.x);
        *(__half*)(tb + SWZ((uint32_t)((dd + 1) * 128 + tt * 2))) = __float2half_rn(f.y);
        *(__half*)(tb + SWZ((uint32_t)((dd + 2) * 128 + tt * 2))) = __float2half_rn(f.z);
        *(__half*)(tb + SWZ((uint32_t)((dd + 3) * 128 + tt * 2))) = __float2half_rn(f.w);
    }
    __syncthreads();
    __half* d0 = g_Vt + ((size_t)((b * 24 + dT) * 32 + kT)) * 8192;
    const uint4* s4 = (const uint4*)tb;
    uint4* g4 = (uint4*)d0;
    for (int i = tid; i < 1024; i += 256) g4[i] = s4[i];
}

// ---------------------------------------------------------------------------
// GEMM: CTA 128x128, K-chunk 64, 3-stage mbarrier cp.async pipeline,
// 256 threads / 8 warps (4m x 2n), warp tile 32x64, 2 CTAs per SM.
// Per stage s: full[s] (256 cp.async.noinc arrivals) and empty[s] (256 thread
// arrivals). A warp starts chunk k as soon as full[k%3] completes -- no
// CTA-wide rendezvous; only the prefetch issue waits for stage reuse.
// MODE 0: exp epilogue -> P (fp16 swizzled) + partial rowsums
// MODE 1: normalize epilogue -> fp32 out
// ---------------------------------------------------------------------------
#define STAGE_BYTES 32768
#define MBAR_OFF    (3 * STAGE_BYTES)
#define SMEM_BYTES  (3 * STAGE_BYTES + 1024)

template<int NK, int NBT, int MODE>
__global__ __launch_bounds__(256, 2) void k_gemm(
    const __half* __restrict__ Ab, const __half* __restrict__ Bb,
    float* __restrict__ out)
{
    extern __shared__ __align__(1024) char sm[];
    const int tid = threadIdx.x, wid = tid >> 5, lane = tid & 31;
    const int nT = blockIdx.x, sT = blockIdx.y, b = blockIdx.z;
    const uint32_t smb = smem_u32(sm);
    const uint32_t MB = smb + MBAR_OFF;          // full(s)=MB+16s, empty=+8
    float* sinv = (float*)(sm + MBAR_OFF + 64);

    const __half* aBase = Ab + ((size_t)(b * 16 + sT) * NK) * 8192;
    const __half* bBase = Bb + ((size_t)(b * NBT + nT) * NK) * 8192;

    if (tid == 0) {
#pragma unroll
        for (int s = 0; s < 3; s++) {
            mbar_init(MB + 16 * s, 256);         // full
            mbar_init(MB + 16 * s + 8, 256);     // empty
        }
    }
    __syncthreads();

    if (MODE == 1 && tid < 128) {
        const float* rr = g_rs + ((size_t)(b * SS) + sT * 128 + tid) * 32;
        float s = 0.f;
#pragma unroll
        for (int i = 0; i < 8; i++) {
            float4 v = *(const float4*)(rr + i * 4);
            s += v.x + v.y + v.z + v.w;
        }
        sinv[tid] = 1.f / s;
    }

    // copy chunk k (A 16KB + B 16KB) into stage k%3 (no commit groups)
    auto issue = [&](int k) {
        uint32_t st = smb + (uint32_t)(k % 3) * STAGE_BYTES;
#pragma unroll
        for (int j = 0; j < 8; j++) {
            int idx = j * 256 + tid;
            int blk = idx >> 10, ru = idx & 1023;
            const char* src = (const char*)((blk ? bBase : aBase) +
                              (size_t)k * 8192) + ru * 16;
            cp16(st + (uint32_t)blk * 16384u + (uint32_t)ru * 16u, src);
        }
    };
    issue(0); cpasync_mbar_arrive(MB + 0);
    issue(1); cpasync_mbar_arrive(MB + 16);

    float acc[2][8][4];
#pragma unroll
    for (int i = 0; i < 2; i++)
#pragma unroll
        for (int j = 0; j < 8; j++)
#pragma unroll
            for (int q = 0; q < 4; q++) acc[i][j][q] = 0.f;

    const int wm = wid & 3, wn = wid >> 2;       // 4 m-groups x 2 n-groups
    const int g2 = lane >> 3, ri = lane & 7;
    const int arow = wm * 32 + (g2 & 1) * 8 + ri;
    const int brow = wn * 64 + (g2 & 1) * 8 + ri;

    // SWZ(row*128+col) = row*128 + (col ^ ((row&7)*16)); fold invariants.
    const uint32_t colhi = (uint32_t)(g2 >> 1) * 16;
    const uint32_t cba = colhi ^ ((uint32_t)(arow & 7) * 16);
    const uint32_t cbb = colhi ^ ((uint32_t)(brow & 7) * 16);
    const uint32_t aoffc = (uint32_t)arow * 128;
    const uint32_t boffc = 16384u + (uint32_t)brow * 128;

    for (int k = 0; k < NK; k++) {
        const int s = k % 3;
        const int kd3 = k / 3;
        mbar_wait(MB + 16 * s, (uint32_t)(kd3 & 1));   // stage s full, acquire
        uint32_t sa = smb + (uint32_t)s * STAGE_BYTES;
#pragma unroll
        for (int kss = 0; kss < 4; kss++) {
            const uint32_t ca = cba ^ (uint32_t)(kss * 32);
            const uint32_t cb = cbb ^ (uint32_t)(kss * 32);
            uint32_t af[2][4], bf[8][2];
#pragma unroll
            for (int mf = 0; mf < 2; mf++)
                ldsm4(af[mf], sa + aoffc + (uint32_t)(mf * 2048) + ca);
#pragma unroll
            for (int f = 0; f < 4; f++) {
                uint32_t tb4[4];
                ldsm4(tb4, sa + boffc + (uint32_t)(f * 2048) + cb);
                bf[2 * f][0] = tb4[0]; bf[2 * f + 1][0] = tb4[1];
                bf[2 * f][1] = tb4[2]; bf[2 * f + 1][1] = tb4[3];
            }
#pragma unroll
            for (int mf = 0; mf < 2; mf++)
#pragma unroll
                for (int nf = 0; nf < 8; nf++)
                    hmma(acc[mf][nf], af[mf], bf[nf]);
        }
        const int kp = k + 2;
        if (kp < NK) {
            const int sp = kp % 3;
            if (kp >= 3)                          // stage reuse: wait empties
                mbar_wait(MB + 16 * sp + 8, (uint32_t)(((kp / 3) - 1) & 1));
            issue(kp);
            cpasync_mbar_arrive(MB + 16 * sp);
        }
        mbar_arrive(MB + 16 * s + 8);             // done reading stage s
    }
    __syncthreads();                              // all warps done; smem reusable

    const int g = lane >> 2, t4 = lane & 3;

    if (MODE == 0) {
#pragma unroll
        for (int mf = 0; mf < 2; mf++) {
#pragma unroll
            for (int hi = 0; hi < 2; hi++) {
                int row = wm * 32 + mf * 16 + hi * 8 + g;
                int sglob = sT * 128 + row;
                float rsum = 0.f;
#pragma unroll
                for (int nf = 0; nf < 8; nf++) {
                    int c = wn * 64 + nf * 8 + 2 * t4;
                    int tg = nT * 128 + c;
                    float x0 = acc[mf][nf][hi * 2]     * SCALE + ((tg     <= sglob) ? 1.f : 0.f);
                    float x1 = acc[mf][nf][hi * 2 + 1] * SCALE + ((tg + 1 <= sglob) ? 1.f : 0.f);
                    float p0 = __expf(x0), p1 = __expf(x1);
                    rsum += p0 + p1;
                    __half2 h = __floats2half2_rn(p0, p1);
                    uint32_t off = (uint32_t)(c >> 6) * 16384 +
                                   SWZ((uint32_t)(row * 128 + (c & 63) * 2));
                    *(__half2*)(sm + off) = h;
                }
                rsum += __shfl_xor_sync(~0u, rsum, 1);
                rsum += __shfl_xor_sync(~0u, rsum, 2);
                if (t4 == 0)
                    g_rs[((size_t)(b * SS) + sglob) * 32 + nT * 2 + wn] = rsum;
            }
        }
        __syncthreads();
        __half* pdst = g_P + ((size_t)((b * 16 + sT) * 32 + nT * 2)) * 8192;
        const uint4* s4 = (const uint4*)sm;
        uint4* g4 = (uint4*)pdst;
        for (int i = tid; i < 2048; i += 256) g4[i] = s4[i];
    } else {
#pragma unroll
        for (int mf = 0; mf < 2; mf++) {
#pragma unroll
            for (int hi = 0; hi < 2; hi++) {
                int row = wm * 32 + mf * 16 + hi * 8 + g;
                float inv = sinv[row];
#pragma unroll
                for (int nf = 0; nf < 8; nf++) {
                    int c = wn * 64 + nf * 8 + 2 * t4;
                    float2 v;
                    v.x = acc[mf][nf][hi * 2]     * inv;
                    v.y = acc[mf][nf][hi * 2 + 1] * inv;
                    *(float2*)(sm + (size_t)(row * 132 + c) * 4) = v;
                }
            }
        }
        __syncthreads();
        float* obase = out + ((size_t)(b * SS) + sT * 128) * DD + nT * 128;
        for (int i = tid; i < 4096; i += 256) {
            int row = i >> 5, c = (i & 31) * 4;
            float4 v = *(const float4*)(sm + (size_t)(row * 132 + c) * 4);
            *(float4*)(obase + (size_t)row * DD + c) = v;
        }
    }
}

// ---------------------------------------------------------------------------
extern "C" void kernel_launch(void* const* d_in, const int* in_sizes, int n_in,
                              void* d_out, int out_size) {
    (void)in_sizes; (void)n_in; (void)out_size;
    const float* q = (const float*)d_in[1];
    const float* k = (const float*)d_in[2];
    const float* v = (const float*)d_in[3];
    float* out = (float*)d_out;

    static int init = 0;
    if (!init) {
        cudaFuncSetAttribute(k_gemm<48, 16, 0>, cudaFuncAttributeMaxDynamicSharedMemorySize, SMEM_BYTES);
        cudaFuncSetAttribute(k_gemm<32, 24, 1>, cudaFuncAttributeMaxDynamicSharedMemorySize, SMEM_BYTES);
        init = 1;
    }

    void *pQ = nullptr, *pK = nullptr, *pVt = nullptr, *pP = nullptr;
    cudaGetSymbolAddress(&pQ, g_Qh);
    cudaGetSymbolAddress(&pK, g_Kh);
    cudaGetSymbolAddress(&pVt, g_Vt);
    cudaGetSymbolAddress(&pP, g_P);

    k_conv_qk<0><<<dim3(48, 16, 16), 256>>>(q);
    k_conv_qk<1><<<dim3(48, 16, 16), 256>>>(k);
    k_conv_v<<<dim3(32, 24, 16), 256>>>(v);
    // GEMM1: logits -> exp -> P + rowsums. grid (nT=16, sT=16, b=16)
    k_gemm<48, 16, 0><<<dim3(16, 16, 16), 256, SMEM_BYTES>>>(
        (const __half*)pQ, (const __half*)pK, nullptr);
    // GEMM2: P @ Vt -> normalized out. grid (nT=24, sT=16, b=16)
    k_gemm<32, 24, 1><<<dim3(24, 16, 16), 256, SMEM_BYTES>>>(
        (const __half*)pP, (const __half*)pVt, out);
}

// round 16
// speedup vs baseline: 1.0708x; 1.0218x over previous
#include <cuda_runtime.h>
#include <cuda_fp16.h>
#include <stdint.h>
#include <stddef.h>

// ---------------------------------------------------------------------------
// out = softmax(Q K^T / sqrt(D) + tril(ones)) V ;  B=16, S=2048, D=3072, fp32
// sm_103 base-target only: cp.async + ldmatrix + mma.sync (no tcgen05/TMA).
// R14 config (best) + micro: early empty-arrive, deferred GEMM2 rowsum load,
// fused single convert kernel.
// ---------------------------------------------------------------------------
#define BB 16
#define SS 2048
#define DD 3072
#define SCALE 0.01804219591217581f  // 1/sqrt(3072)

__device__ __align__(128) __half g_Qh[(size_t)BB * SS * DD];   // (b, sT16, kT48)
__device__ __align__(128) __half g_Kh[(size_t)BB * SS * DD];   // (b, tT16, kT48)
__device__ __align__(128) __half g_Vt[(size_t)BB * SS * DD];   // (b, dT24, kT32) row=d,col=t
__device__ __align__(128) __half g_P [(size_t)BB * SS * SS];   // (b, sT16, tT32)
__device__ __align__(128) float  g_rs[(size_t)BB * SS * 32];   // 32 partial rowsums per row

#define SWZ(o) ((o) ^ (((o) >> 3) & 0x70))

static __device__ __forceinline__ uint32_t smem_u32(const void* p) {
    uint32_t a;
    asm("{ .reg .u64 t; cvta.to.shared.u64 t, %1; cvt.u32.u64 %0, t; }" : "=r"(a) : "l"(p));
    return a;
}
static __device__ __forceinline__ void cp16(uint32_t dst, const void* src) {
    unsigned long long g = __cvta_generic_to_global(src);
    asm volatile("cp.async.cg.shared.global [%0], [%1], 16;" :: "r"(dst), "l"(g) : "memory");
}
static __device__ __forceinline__ void mbar_init(uint32_t a, uint32_t c) {
    asm volatile("mbarrier.init.shared.b64 [%0], %1;" :: "r"(a), "r"(c) : "memory");
}
static __device__ __forceinline__ void mbar_arrive(uint32_t a) {
    asm volatile("mbarrier.arrive.shared.b64 _, [%0];" :: "r"(a) : "memory");
}
// arrive on mbar once all of THIS thread's prior cp.asyncs have completed
static __device__ __forceinline__ void cpasync_mbar_arrive(uint32_t a) {
    asm volatile("cp.async.mbarrier.arrive.noinc.shared::cta.b64 [%0];" :: "r"(a) : "memory");
}
static __device__ __forceinline__ void mbar_wait(uint32_t mbar, uint32_t parity) {
    uint32_t done = 0;
    while (!done) {
        asm volatile(
            "{\n\t.reg .pred p;\n\t"
            "mbarrier.try_wait.parity.acquire.cta.shared::cta.b64 p, [%1], %2, 0x989680;\n\t"
            "selp.b32 %0, 1, 0, p;\n\t}"
            : "=r"(done) : "r"(mbar), "r"(parity) : "memory");
    }
}

static __device__ __forceinline__ void ldsm4(uint32_t* r, uint32_t addr) {
    asm volatile("ldmatrix.sync.aligned.m8n8.x4.shared.b16 {%0,%1,%2,%3}, [%4];"
                 : "=r"(r[0]), "=r"(r[1]), "=r"(r[2]), "=r"(r[3]) : "r"(addr));
}
static __device__ __forceinline__ void hmma(float* d, const uint32_t* a, const uint32_t* b) {
    asm volatile(
        "mma.sync.aligned.m16n8k16.row.col.f32.f16.f16.f32 "
        "{%0,%1,%2,%3}, {%4,%5,%6,%7}, {%8,%9}, {%0,%1,%2,%3};"
        : "+f"(d[0]), "+f"(d[1]), "+f"(d[2]), "+f"(d[3])
        : "r"(a[0]), "r"(a[1]), "r"(a[2]), "r"(a[3]), "r"(b[0]), "r"(b[1]));
}

// ---------------------------------------------------------------------------
// Fused fp32 -> fp16 block-swizzled convert for Q, K and V (one kernel, one
// wave-tail). grid (48, 56, 16): y<16 Q(sT=y), y<32 K(sT=y-16),
// y>=32 V(dT=y-32, x<32 only).
// ---------------------------------------------------------------------------
__global__ __launch_bounds__(256) void k_conv_all(
    const float* __restrict__ q, const float* __restrict__ k,
    const float* __restrict__ v)
{
    __shared__ __align__(16) char tb[16384];
    const int job = blockIdx.y, b = blockIdx.z, tid = threadIdx.x;
    if (job < 32) {
        const float* src = (job < 16) ? q : k;
        __half* dst = (job < 16) ? g_Qh : g_Qh + 0;   // placeholder; fixed below
        dst = (job < 16) ? g_Qh : g_Kh;
        const int sT = job & 15, kT = blockIdx.x;
        const float* s0 = src + ((size_t)(b * SS) + sT * 128) * DD + kT * 64;
        __half* d0 = dst + ((size_t)((b * 16 + sT) * 48 + kT)) * 8192;
#pragma unroll
        for (int j = 0; j < 4; j++) {
            int e = (j * 256 + tid) * 8;
            int r = e >> 6, c = e & 63;
            const float4* p = (const float4*)(s0 + (size_t)r * DD + c);
            float4 f0 = p[0], f1 = p[1];
            __half2 h0 = __floats2half2_rn(f0.x, f0.y), h1 = __floats2half2_rn(f0.z, f0.w);
            __half2 h2 = __floats2half2_rn(f1.x, f1.y), h3 = __floats2half2_rn(f1.z, f1.w);
            uint4 u;
            u.x = *(const uint32_t*)&h0; u.y = *(const uint32_t*)&h1;
            u.z = *(const uint32_t*)&h2; u.w = *(const uint32_t*)&h3;
            *(uint4*)((char*)d0 + SWZ((uint32_t)(r * 128 + c * 2))) = u;
        }
    } else {
        if (blockIdx.x >= 32) return;
        const int dT = job - 32, kT = blockIdx.x;
        const float* s0 = v + ((size_t)(b * SS) + kT * 64) * DD + dT * 128;
#pragma unroll
        for (int j = 0; j < 8; j++) {
            int e = (j * 256 + tid) * 4;
            int tt = e >> 7, dd = e & 127;
            float4 f = *(const float4*)(s0 + (size_t)tt * DD + dd);
            *(__half*)(tb + SWZ((uint32_t)((dd + 0) * 128 + tt * 2))) = __float2half_rn(f.x);
            *(__half*)(tb + SWZ((uint32_t)((dd + 1) * 128 + tt * 2))) = __float2half_rn(f.y);
            *(__half*)(tb + SWZ((uint32_t)((dd + 2) * 128 + tt * 2))) = __float2half_rn(f.z);
            *(__half*)(tb + SWZ((uint32_t)((dd + 3) * 128 + tt * 2))) = __float2half_rn(f.w);
        }
        __syncthreads();
        __half* d0 = g_Vt + ((size_t)((b * 24 + dT) * 32 + kT)) * 8192;
        const uint4* s4 = (const uint4*)tb;
        uint4* g4 = (uint4*)d0;
        for (int i = tid; i < 1024; i += 256) g4[i] = s4[i];
    }
}

// ---------------------------------------------------------------------------
// GEMM: CTA 128x128, K-chunk 64, 3-stage mbarrier cp.async pipeline,
// 256 threads / 8 warps (4m x 2n), warp tile 32x64, 2 CTAs per SM.
// MODE 0: exp epilogue -> P (fp16 swizzled) + partial rowsums
// MODE 1: normalize epilogue -> fp32 out (rowsum load deferred past issue)
// ---------------------------------------------------------------------------
#define STAGE_BYTES 32768
#define MBAR_OFF    (3 * STAGE_BYTES)
#define SMEM_BYTES  (3 * STAGE_BYTES + 1024)

template<int NK, int NBT, int MODE>
__global__ __launch_bounds__(256, 2) void k_gemm(
    const __half* __restrict__ Ab, const __half* __restrict__ Bb,
    float* __restrict__ out)
{
    extern __shared__ __align__(1024) char sm[];
    const int tid = threadIdx.x, wid = tid >> 5, lane = tid & 31;
    const int nT = blockIdx.x, sT = blockIdx.y, b = blockIdx.z;
    const uint32_t smb = smem_u32(sm);
    const uint32_t MB = smb + MBAR_OFF;          // full(s)=MB+16s, empty=+8
    float* sinv = (float*)(sm + MBAR_OFF + 64);

    const __half* aBase = Ab + ((size_t)(b * 16 + sT) * NK) * 8192;
    const __half* bBase = Bb + ((size_t)(b * NBT + nT) * NK) * 8192;

    if (tid == 0) {
#pragma unroll
        for (int s = 0; s < 3; s++) {
            mbar_init(MB + 16 * s, 256);         // full
            mbar_init(MB + 16 * s + 8, 256);     // empty
        }
    }
    __syncthreads();

    // copy chunk k (A 16KB + B 16KB) into stage k%3 (no commit groups)
    auto issue = [&](int k) {
        uint32_t st = smb + (uint32_t)(k % 3) * STAGE_BYTES;
#pragma unroll
        for (int j = 0; j < 8; j++) {
            int idx = j * 256 + tid;
            int blk = idx >> 10, ru = idx & 1023;
            const char* src = (const char*)((blk ? bBase : aBase) +
                              (size_t)k * 8192) + ru * 16;
            cp16(st + (uint32_t)blk * 16384u + (uint32_t)ru * 16u, src);
        }
    };
    issue(0); cpasync_mbar_arrive(MB + 0);
    issue(1); cpasync_mbar_arrive(MB + 16);

    if (MODE == 1 && tid < 128) {                // after pipeline start
        const float* rr = g_rs + ((size_t)(b * SS) + sT * 128 + tid) * 32;
        float s = 0.f;
#pragma unroll
        for (int i = 0; i < 8; i++) {
            float4 v = *(const float4*)(rr + i * 4);
            s += v.x + v.y + v.z + v.w;
        }
        sinv[tid] = 1.f / s;
    }

    float acc[2][8][4];
#pragma unroll
    for (int i = 0; i < 2; i++)
#pragma unroll
        for (int j = 0; j < 8; j++)
#pragma unroll
            for (int q = 0; q < 4; q++) acc[i][j][q] = 0.f;

    const int wm = wid & 3, wn = wid >> 2;       // 4 m-groups x 2 n-groups
    const int g2 = lane >> 3, ri = lane & 7;
    const int arow = wm * 32 + (g2 & 1) * 8 + ri;
    const int brow = wn * 64 + (g2 & 1) * 8 + ri;

    // SWZ(row*128+col) = row*128 + (col ^ ((row&7)*16)); fold invariants.
    const uint32_t colhi = (uint32_t)(g2 >> 1) * 16;
    const uint32_t cba = colhi ^ ((uint32_t)(arow & 7) * 16);
    const uint32_t cbb = colhi ^ ((uint32_t)(brow & 7) * 16);
    const uint32_t aoffc = (uint32_t)arow * 128;
    const uint32_t boffc = 16384u + (uint32_t)brow * 128;

    for (int k = 0; k < NK; k++) {
        const int s = k % 3;
        const int kd3 = k / 3;
        mbar_wait(MB + 16 * s, (uint32_t)(kd3 & 1));   // stage s full, acquire
        uint32_t sa = smb + (uint32_t)s * STAGE_BYTES;
#pragma unroll
        for (int kss = 0; kss < 4; kss++) {
            const uint32_t ca = cba ^ (uint32_t)(kss * 32);
            const uint32_t cb = cbb ^ (uint32_t)(kss * 32);
            uint32_t af[2][4], bf[8][2];
#pragma unroll
            for (int mf = 0; mf < 2; mf++)
                ldsm4(af[mf], sa + aoffc + (uint32_t)(mf * 2048) + ca);
#pragma unroll
            for (int f = 0; f < 4; f++) {
                uint32_t tb4[4];
                ldsm4(tb4, sa + boffc + (uint32_t)(f * 2048) + cb);
                bf[2 * f][0] = tb4[0]; bf[2 * f + 1][0] = tb4[1];
                bf[2 * f][1] = tb4[2]; bf[2 * f + 1][1] = tb4[3];
            }
#pragma unroll
            for (int mf = 0; mf < 2; mf++)
#pragma unroll
                for (int nf = 0; nf < 8; nf++)
                    hmma(acc[mf][nf], af[mf], bf[nf]);
        }
        mbar_arrive(MB + 16 * s + 8);             // done reading stage s (early)
        const int kp = k + 2;
        if (kp < NK) {
            const int sp = kp % 3;
            if (kp >= 3)                          // stage reuse: wait empties
                mbar_wait(MB + 16 * sp + 8, (uint32_t)(((kp / 3) - 1) & 1));
            issue(kp);
            cpasync_mbar_arrive(MB + 16 * sp);
        }
    }
    __syncthreads();                              // all warps done; smem reusable

    const int g = lane >> 2, t4 = lane & 3;

    if (MODE == 0) {
#pragma unroll
        for (int mf = 0; mf < 2; mf++) {
#pragma unroll
            for (int hi = 0; hi < 2; hi++) {
                int row = wm * 32 + mf * 16 + hi * 8 + g;
                int sglob = sT * 128 + row;
                float rsum = 0.f;
#pragma unroll
                for (int nf = 0; nf < 8; nf++) {
                    int c = wn * 64 + nf * 8 + 2 * t4;
                    int tg = nT * 128 + c;
                    float x0 = acc[mf][nf][hi * 2]     * SCALE + ((tg     <= sglob) ? 1.f : 0.f);
                    float x1 = acc[mf][nf][hi * 2 + 1] * SCALE + ((tg + 1 <= sglob) ? 1.f : 0.f);
                    float p0 = __expf(x0), p1 = __expf(x1);
                    rsum += p0 + p1;
                    __half2 h = __floats2half2_rn(p0, p1);
                    uint32_t off = (uint32_t)(c >> 6) * 16384 +
                                   SWZ((uint32_t)(row * 128 + (c & 63) * 2));
                    *(__half2*)(sm + off) = h;
                }
                rsum += __shfl_xor_sync(~0u, rsum, 1);
                rsum += __shfl_xor_sync(~0u, rsum, 2);
                if (t4 == 0)
                    g_rs[((size_t)(b * SS) + sglob) * 32 + nT * 2 + wn] = rsum;
            }
        }
        __syncthreads();
        __half* pdst = g_P + ((size_t)((b * 16 + sT) * 32 + nT * 2)) * 8192;
        const uint4* s4 = (const uint4*)sm;
        uint4* g4 = (uint4*)pdst;
        for (int i = tid; i < 2048; i += 256) g4[i] = s4[i];
    } else {
#pragma unroll
        for (int mf = 0; mf < 2; mf++) {
#pragma unroll
            for (int hi = 0; hi < 2; hi++) {
                int row = wm * 32 + mf * 16 + hi * 8 + g;
                float inv = sinv[row];
#pragma unroll
                for (int nf = 0; nf < 8; nf++) {
                    int c = wn * 64 + nf * 8 + 2 * t4;
                    float2 v;
                    v.x = acc[mf][nf][hi * 2]     * inv;
                    v.y = acc[mf][nf][hi * 2 + 1] * inv;
                    *(float2*)(sm + (size_t)(row * 132 + c) * 4) = v;
                }
            }
        }
        __syncthreads();
        float* obase = out + ((size_t)(b * SS) + sT * 128) * DD + nT * 128;
        for (int i = tid; i < 4096; i += 256) {
            int row = i >> 5, c = (i & 31) * 4;
            float4 v = *(const float4*)(sm + (size_t)(row * 132 + c) * 4);
            *(float4*)(obase + (size_t)row * DD + c) = v;
        }
    }
}

// ---------------------------------------------------------------------------
extern "C" void kernel_launch(void* const* d_in, const int* in_sizes, int n_in,
                              void* d_out, int out_size) {
    (void)in_sizes; (void)n_in; (void)out_size;
    const float* q = (const float*)d_in[1];
    const float* k = (const float*)d_in[2];
    const float* v = (const float*)d_in[3];
    float* out = (float*)d_out;

    static int init = 0;
    if (!init) {
        cudaFuncSetAttribute(k_gemm<48, 16, 0>, cudaFuncAttributeMaxDynamicSharedMemorySize, SMEM_BYTES);
        cudaFuncSetAttribute(k_gemm<32, 24, 1>, cudaFuncAttributeMaxDynamicSharedMemorySize, SMEM_BYTES);
        init = 1;
    }

    void *pQ = nullptr, *pK = nullptr, *pVt = nullptr, *pP = nullptr;
    cudaGetSymbolAddress(&pQ, g_Qh);
    cudaGetSymbolAddress(&pK, g_Kh);
    cudaGetSymbolAddress(&pVt, g_Vt);
    cudaGetSymbolAddress(&pP, g_P);

    // All three converts in one launch (one wave-tail instead of three).
    k_conv_all<<<dim3(48, 56, 16), 256>>>(q, k, v);
    // GEMM1: logits -> exp -> P + rowsums. grid (nT=16, sT=16, b=16)
    k_gemm<48, 16, 0><<<dim3(16, 16, 16), 256, SMEM_BYTES>>>(
        (const __half*)pQ, (const __half*)pK, nullptr);
    // GEMM2: P @ Vt -> normalized out. grid (nT=24, sT=16, b=16)
    k_gemm<32, 24, 1><<<dim3(24, 16, 16), 256, SMEM_BYTES>>>(
        (const __half*)pP, (const __half*)pVt, out);
}